// round 2
// baseline (speedup 1.0000x reference)
#include <cuda_runtime.h>
#include <math.h>

#define NN 20000
#define EE 160000
#define OUTD 256
#define INDIM 256
#define NH 8
#define DK 32

// ---------------- scratch (device globals; no allocation allowed) ----------------
__device__ float g_K[NN * OUTD];
__device__ float g_Q[NN * OUTD];
__device__ float g_V[NN * OUTD];
__device__ float g_MK[NN * OUTD];
__device__ float g_VAL[3 * NN * OUTD];
__device__ float g_CVAL[3 * NN * OUTD];
__device__ float g_EA[3 * EE * NH];
__device__ float g_ECA[3 * EE * NH];
__device__ float g_SA[3 * NN * NH];
__device__ float g_SCA[3 * NN * NH];

// ---------------- helpers ----------------
__device__ __forceinline__ void red_add_v4(float* p, float a, float b, float c, float d) {
    asm volatile("red.global.add.v4.f32 [%0], {%1,%2,%3,%4};"
                 :: "l"(p), "f"(a), "f"(b), "f"(c), "f"(d) : "memory");
}

// ---------------- kernel 0: zero accumulators ----------------
__global__ void zero_kernel(float* __restrict__ out) {
    int stride = gridDim.x * blockDim.x;
    for (int i = blockIdx.x * blockDim.x + threadIdx.x; i < NN * OUTD; i += stride)
        out[i] = 0.0f;
    for (int i = blockIdx.x * blockDim.x + threadIdx.x; i < 3 * NN * NH; i += stride) {
        g_SA[i] = 0.0f;
        g_SCA[i] = 0.0f;
    }
}

// ---------------- kernel 1: fused QKV GEMM ----------------
// C[N, 768] = x @ [Wk | Wq | Wv] + [bk | bq | bv], split into g_K/g_Q/g_V
// 64x64 block tile, 16 k-chunk, 4x4 per thread, 256 threads.
__global__ void __launch_bounds__(256) gemm_qkv(
    const float* __restrict__ x,
    const float* __restrict__ Wk, const float* __restrict__ bk,
    const float* __restrict__ Wq, const float* __restrict__ bq,
    const float* __restrict__ Wv, const float* __restrict__ bv)
{
    __shared__ float As[16][64];
    __shared__ float Bs[16][64];

    int t = threadIdx.x;
    int tx = t & 15, ty = t >> 4;
    int rowBase = blockIdx.y * 64;
    int cb = blockIdx.x * 64;

    const float* W; const float* bias; float* out;
    if (cb < 256)      { W = Wk; bias = bk; out = g_K; }
    else if (cb < 512) { W = Wq; bias = bq; out = g_Q; cb -= 256; }
    else               { W = Wv; bias = bv; out = g_V; cb -= 512; }

    float acc[4][4];
#pragma unroll
    for (int i = 0; i < 4; i++)
#pragma unroll
        for (int j = 0; j < 4; j++) acc[i][j] = 0.0f;

    int lr = t >> 2;           // 0..63  row for A load
    int lk = (t & 3) * 4;      // 0,4,8,12
    int brow = t >> 4;         // 0..15  k for B load
    int bcol = (t & 15) * 4;   // 0..60

    for (int k0 = 0; k0 < INDIM; k0 += 16) {
        float4 av = make_float4(0.f, 0.f, 0.f, 0.f);
        int gr = rowBase + lr;
        if (gr < NN) av = *(const float4*)&x[gr * INDIM + k0 + lk];
        As[lk + 0][lr] = av.x;
        As[lk + 1][lr] = av.y;
        As[lk + 2][lr] = av.z;
        As[lk + 3][lr] = av.w;

        *(float4*)&Bs[brow][bcol] = *(const float4*)&W[(k0 + brow) * 256 + cb + bcol];
        __syncthreads();

#pragma unroll
        for (int kk = 0; kk < 16; kk++) {
            float4 a = *(float4*)&As[kk][ty * 4];
            float4 b = *(float4*)&Bs[kk][tx * 4];
            acc[0][0] += a.x * b.x; acc[0][1] += a.x * b.y; acc[0][2] += a.x * b.z; acc[0][3] += a.x * b.w;
            acc[1][0] += a.y * b.x; acc[1][1] += a.y * b.y; acc[1][2] += a.y * b.z; acc[1][3] += a.y * b.w;
            acc[2][0] += a.z * b.x; acc[2][1] += a.z * b.y; acc[2][2] += a.z * b.z; acc[2][3] += a.z * b.w;
            acc[3][0] += a.w * b.x; acc[3][1] += a.w * b.y; acc[3][2] += a.w * b.z; acc[3][3] += a.w * b.w;
        }
        __syncthreads();
    }

#pragma unroll
    for (int i = 0; i < 4; i++) {
        int r = rowBase + ty * 4 + i;
        if (r < NN) {
#pragma unroll
            for (int j = 0; j < 4; j++) {
                int c = cb + tx * 4 + j;
                out[r * OUTD + c] = acc[i][j] + bias[c];
            }
        }
    }
}

// ---------------- kernel 2: node-level relation transforms ----------------
// Per (node, head): 32x32 matvecs.
//   warp 0..2 : masked_k with cau_filter[ct] (warp w handles nodes with ct==w)
//   warp 3..5 : val_e   = v @ msg[e]
//   warp 6..8 : cval_e  = (v + time_emb) @ msg_cau[e]
// Each lane holds one matrix column in registers; k/v rows broadcast from smem.
__global__ void __launch_bounds__(288) transform_kernel(
    const float* __restrict__ msg, const float* __restrict__ msg_cau,
    const float* __restrict__ cau_filter, const float* __restrict__ time_emb,
    const int* __restrict__ cau_type)
{
    __shared__ float k_s[32][32];
    __shared__ float v_s[32][32];
    __shared__ float vt_s[32][32];
    __shared__ int ct_s[32];

    int h = blockIdx.y;
    int nodeBase = blockIdx.x * 32;
    int tid = threadIdx.x;

    for (int idx = tid; idx < 32 * 32; idx += 288) {
        int n = idx >> 5, dcol = idx & 31;
        int gn = nodeBase + n;
        float kv = 0.f, vv = 0.f;
        if (gn < NN) {
            kv = g_K[gn * OUTD + h * 32 + dcol];
            vv = g_V[gn * OUTD + h * 32 + dcol];
        }
        k_s[n][dcol] = kv;
        v_s[n][dcol] = vv;
        vt_s[n][dcol] = vv + time_emb[h * 32 + dcol];
    }
    for (int idx = tid; idx < 32; idx += 288) {
        int gn = nodeBase + idx;
        ct_s[idx] = (gn < NN) ? cau_type[gn] : -1;
    }
    __syncthreads();

    int wid = tid >> 5, lane = tid & 31;
    const float* mat;
    const float (*srcm)[32];
    float* outp;
    int myct = -1;
    if (wid < 3) {
        mat = cau_filter + (wid * NH + h) * 1024;
        srcm = k_s; outp = g_MK; myct = wid;
    } else if (wid < 6) {
        int e = wid - 3;
        mat = msg + (e * NH + h) * 1024;
        srcm = v_s; outp = g_VAL + e * NN * OUTD;
    } else {
        int e = wid - 6;
        mat = msg_cau + (e * NH + h) * 1024;
        srcm = vt_s; outp = g_CVAL + e * NN * OUTD;
    }

    float mcol[32];
#pragma unroll
    for (int d = 0; d < 32; d++) mcol[d] = mat[d * 32 + lane];  // coalesced per d

    for (int n = 0; n < 32; n++) {
        int gn = nodeBase + n;
        if (gn >= NN) break;
        if (myct >= 0 && ct_s[n] != myct) continue;
        float acc = 0.f;
#pragma unroll
        for (int d4 = 0; d4 < 8; d4++) {
            float4 sv = *(const float4*)&srcm[n][d4 * 4];  // broadcast LDS.128
            acc += sv.x * mcol[d4 * 4 + 0];
            acc += sv.y * mcol[d4 * 4 + 1];
            acc += sv.z * mcol[d4 * 4 + 2];
            acc += sv.w * mcol[d4 * 4 + 3];
        }
        outp[gn * OUTD + h * 32 + lane] = acc;
    }
}

// ---------------- kernel 3: edge logits + softmax denominators ----------------
// One warp per edge. Lanes 4h..4h+3 cover head h's 32 dims (8 each).
// No segment-max: logits are O(1) scale, exp() is safe, softmax shift-invariant.
__global__ void __launch_bounds__(256) logits_kernel(
    const int* __restrict__ src, const int* __restrict__ dst,
    const float* __restrict__ pri, const float* __restrict__ pri_cau)
{
    int e = blockIdx.y;
    int edge = blockIdx.x * 8 + (threadIdx.x >> 5);
    if (edge >= EE) return;
    int lane = threadIdx.x & 31;
    int s = src[e * EE + edge];
    int d = dst[e * EE + edge];
    int off = lane * 8;

    float4 q0 = *(const float4*)&g_Q[d * OUTD + off];
    float4 q1 = *(const float4*)&g_Q[d * OUTD + off + 4];
    float4 k0 = *(const float4*)&g_K[s * OUTD + off];
    float4 k1 = *(const float4*)&g_K[s * OUTD + off + 4];
    float4 m0 = *(const float4*)&g_MK[s * OUTD + off];
    float4 m1 = *(const float4*)&g_MK[s * OUTD + off + 4];

    float sqk = q0.x * k0.x + q0.y * k0.y + q0.z * k0.z + q0.w * k0.w
              + q1.x * k1.x + q1.y * k1.y + q1.z * k1.z + q1.w * k1.w;
    float sqm = q0.x * m0.x + q0.y * m0.y + q0.z * m0.z + q0.w * m0.w
              + q1.x * m1.x + q1.y * m1.y + q1.z * m1.z + q1.w * m1.w;

    sqk += __shfl_xor_sync(0xffffffffu, sqk, 1);
    sqk += __shfl_xor_sync(0xffffffffu, sqk, 2);
    sqm += __shfl_xor_sync(0xffffffffu, sqm, 1);
    sqm += __shfl_xor_sync(0xffffffffu, sqm, 2);

    int hh = lane >> 2;
    const float inv_sqrt_dk = 0.17677669529663687f;  // 1/sqrt(32)
    float ea  = expf(sqk * pri[e * NH + hh] * inv_sqrt_dk);
    float eca = expf(sqm * pri_cau[e * NH + hh] * inv_sqrt_dk);

    if ((lane & 3) == 0) {
        g_EA [(e * EE + edge) * NH + hh] = ea;
        g_ECA[(e * EE + edge) * NH + hh] = eca;
        atomicAdd(&g_SA [(e * NN + d) * NH + hh], ea);
        atomicAdd(&g_SCA[(e * NN + d) * NH + hh], eca);
    }
}

// ---------------- kernel 4: weighted aggregation ----------------
// One warp per edge; vectorized red.global.add into d_out (accumulator).
__global__ void __launch_bounds__(256) aggregate_kernel(
    const int* __restrict__ src, const int* __restrict__ dst,
    const float* __restrict__ comb_pri, float* __restrict__ out)
{
    int e = blockIdx.y;
    int edge = blockIdx.x * 8 + (threadIdx.x >> 5);
    if (edge >= EE) return;
    int lane = threadIdx.x & 31;
    int s = src[e * EE + edge];
    int d = dst[e * EE + edge];
    int hh = lane >> 2;

    float ea  = g_EA [(e * EE + edge) * NH + hh];
    float eca = g_ECA[(e * EE + edge) * NH + hh];
    float wa = ea  / g_SA [(e * NN + d) * NH + hh];
    float wc = eca / g_SCA[(e * NN + d) * NH + hh];

    int off = lane * 8;
    const float* vp = g_VAL  + e * NN * OUTD + s * OUTD + off;
    const float* cp = g_CVAL + e * NN * OUTD + s * OUTD + off;
    float4 v0 = *(const float4*)vp;
    float4 v1 = *(const float4*)(vp + 4);
    float4 c0 = *(const float4*)cp;
    float4 c1 = *(const float4*)(cp + 4);
    float4 b0 = *(const float4*)&comb_pri[e * OUTD + off];
    float4 b1 = *(const float4*)&comb_pri[e * OUTD + off + 4];

    float r0 = wa * v0.x + wc * b0.x * c0.x;
    float r1 = wa * v0.y + wc * b0.y * c0.y;
    float r2 = wa * v0.z + wc * b0.z * c0.z;
    float r3 = wa * v0.w + wc * b0.w * c0.w;
    float r4 = wa * v1.x + wc * b1.x * c1.x;
    float r5 = wa * v1.y + wc * b1.y * c1.y;
    float r6 = wa * v1.z + wc * b1.z * c1.z;
    float r7 = wa * v1.w + wc * b1.w * c1.w;

    float* op = out + d * OUTD + off;
    red_add_v4(op, r0, r1, r2, r3);
    red_add_v4(op + 4, r4, r5, r6, r7);
}

// ---------------- kernel 5: finalize (mean over 3 etypes + relu) ----------------
__global__ void finalize_kernel(float* __restrict__ out) {
    int i = blockIdx.x * blockDim.x + threadIdx.x;
    if (i < NN * OUTD) {
        float v = out[i] * (1.0f / 3.0f);
        out[i] = v > 0.0f ? v : 0.0f;
    }
}

// ---------------- launch ----------------
extern "C" void kernel_launch(void* const* d_in, const int* in_sizes, int n_in,
                              void* d_out, int out_size) {
    const float* x          = (const float*)d_in[0];
    const float* Wk         = (const float*)d_in[1];
    const float* bk         = (const float*)d_in[2];
    const float* Wq         = (const float*)d_in[3];
    const float* bq         = (const float*)d_in[4];
    const float* Wv         = (const float*)d_in[5];
    const float* bv         = (const float*)d_in[6];
    const float* pri        = (const float*)d_in[7];
    const float* msg        = (const float*)d_in[8];
    const float* pri_cau    = (const float*)d_in[9];
    const float* msg_cau    = (const float*)d_in[10];
    const float* comb_pri   = (const float*)d_in[11];
    const float* cau_filter = (const float*)d_in[12];
    const float* time_emb   = (const float*)d_in[13];
    const int*   cau_type   = (const int*)d_in[14];
    const int*   src        = (const int*)d_in[15];
    const int*   dst        = (const int*)d_in[16];
    float* out = (float*)d_out;

    zero_kernel<<<2048, 256>>>(out);

    dim3 ggrid(768 / 64, (NN + 63) / 64);
    gemm_qkv<<<ggrid, 256>>>(x, Wk, bk, Wq, bq, Wv, bv);

    dim3 tgrid((NN + 31) / 32, NH);
    transform_kernel<<<tgrid, 288>>>(msg, msg_cau, cau_filter, time_emb, cau_type);

    dim3 egrid((EE + 7) / 8, 3);
    logits_kernel<<<egrid, 256>>>(src, dst, pri, pri_cau);
    aggregate_kernel<<<egrid, 256>>>(src, dst, comb_pri, out);

    finalize_kernel<<<(NN * OUTD + 255) / 256, 256>>>(out);
}

// round 3
// speedup vs baseline: 1.1512x; 1.1512x over previous
#include <cuda_runtime.h>
#include <math.h>

#define NN 20000
#define EE 160000
#define OUTD 256
#define INDIM 256
#define NH 8

typedef unsigned long long ull;

// ---------------- scratch (device globals; no allocation allowed) ----------------
__device__ float g_K[NN * OUTD];
__device__ float g_Q[NN * OUTD];
__device__ float g_V[NN * OUTD];
__device__ float g_MK[NN * OUTD];
__device__ float g_VAL[3 * NN * OUTD];
__device__ float g_CVAL[3 * NN * OUTD];
__device__ float2 g_E[3 * EE * NH];   // (ea, eca) per edge-head
__device__ float2 g_S[3 * NN * NH];   // (sum_ea, sum_eca) per dst-head

// ---------------- f32x2 helpers (Blackwell packed dual-FP32) ----------------
__device__ __forceinline__ ull pack2(float a, float b) {
    ull r; asm("mov.b64 %0, {%1, %2};" : "=l"(r) : "f"(a), "f"(b)); return r;
}
__device__ __forceinline__ void fma2(ull& acc, ull a, ull b) {
    asm("fma.rn.f32x2 %0, %1, %2, %0;" : "+l"(acc) : "l"(a), "l"(b));
}
__device__ __forceinline__ float2 unpack2(ull v) {
    float2 f; asm("mov.b64 {%0, %1}, %2;" : "=f"(f.x), "=f"(f.y) : "l"(v)); return f;
}
__device__ __forceinline__ void red_add_v4(float* p, float a, float b, float c, float d) {
    asm volatile("red.global.add.v4.f32 [%0], {%1,%2,%3,%4};"
                 :: "l"(p), "f"(a), "f"(b), "f"(c), "f"(d) : "memory");
}
__device__ __forceinline__ void red_add_v2(float2* p, float a, float b) {
    asm volatile("red.global.add.v2.f32 [%0], {%1,%2};"
                 :: "l"(p), "f"(a), "f"(b) : "memory");
}

// ---------------- kernel 0: zero accumulators ----------------
__global__ void zero_kernel(float* __restrict__ out) {
    int stride = gridDim.x * blockDim.x;
    for (int i = blockIdx.x * blockDim.x + threadIdx.x; i < NN * OUTD; i += stride)
        out[i] = 0.0f;
    float2 z2 = make_float2(0.f, 0.f);
    for (int i = blockIdx.x * blockDim.x + threadIdx.x; i < 3 * NN * NH; i += stride)
        g_S[i] = z2;
}

// ---------------- kernel 1: fused QKV GEMM (f32x2) ----------------
// C[N, 768] = x @ [Wk|Wq|Wv] + bias. 128x128 tile, BK=8, 256 threads,
// 8x8 microtile computed as 4 packed row-pairs x 8 cols via fma.rn.f32x2.
#define BM 128
#define BN 128
#define BK 8
__global__ void __launch_bounds__(256) gemm_qkv(
    const float* __restrict__ x,
    const float* __restrict__ Wk, const float* __restrict__ bk,
    const float* __restrict__ Wq, const float* __restrict__ bq,
    const float* __restrict__ Wv, const float* __restrict__ bv)
{
    __shared__ float As[BK][BM + 4];
    __shared__ float Bs[BK][BN + 4];

    int t = threadIdx.x;
    int tx = t & 15, ty = t >> 4;       // 16x16 thread grid
    int rowBase = blockIdx.y * BM;
    int cb = blockIdx.x * BN;           // 0..767

    const float* W; const float* bias; float* out;
    if (cb < 256)      { W = Wk; bias = bk; out = g_K; }
    else if (cb < 512) { W = Wq; bias = bq; out = g_Q; cb -= 256; }
    else               { W = Wv; bias = bv; out = g_V; cb -= 512; }

    int ar = t >> 1;            // 0..127 : A row
    int ak = (t & 1) * 4;       // 0 or 4 : A k-offset
    int bkr = t >> 5;           // 0..7   : B k-row
    int bc  = (t & 31) * 4;     // 0..124 : B col

    ull acc[4][8];
#pragma unroll
    for (int i = 0; i < 4; i++)
#pragma unroll
        for (int j = 0; j < 8; j++) acc[i][j] = 0ull;

    for (int k0 = 0; k0 < INDIM; k0 += BK) {
        float4 av = make_float4(0.f, 0.f, 0.f, 0.f);
        int gr = rowBase + ar;
        if (gr < NN) av = *(const float4*)&x[gr * INDIM + k0 + ak];
        As[ak + 0][ar] = av.x;
        As[ak + 1][ar] = av.y;
        As[ak + 2][ar] = av.z;
        As[ak + 3][ar] = av.w;

        *(float4*)&Bs[bkr][bc] = *(const float4*)&W[(k0 + bkr) * 256 + cb + bc];
        __syncthreads();

#pragma unroll
        for (int kk = 0; kk < BK; kk++) {
            ull a2[4];
#pragma unroll
            for (int i = 0; i < 4; i++)
                a2[i] = *(const ull*)&As[kk][ty * 8 + 2 * i];
            float4 b0 = *(const float4*)&Bs[kk][tx * 8];
            float4 b1 = *(const float4*)&Bs[kk][tx * 8 + 4];
            ull bb[8];
            bb[0] = pack2(b0.x, b0.x); bb[1] = pack2(b0.y, b0.y);
            bb[2] = pack2(b0.z, b0.z); bb[3] = pack2(b0.w, b0.w);
            bb[4] = pack2(b1.x, b1.x); bb[5] = pack2(b1.y, b1.y);
            bb[6] = pack2(b1.z, b1.z); bb[7] = pack2(b1.w, b1.w);
#pragma unroll
            for (int i = 0; i < 4; i++)
#pragma unroll
                for (int j = 0; j < 8; j++)
                    fma2(acc[i][j], a2[i], bb[j]);
        }
        __syncthreads();
    }

    int c0 = cb + tx * 8;
    float4 bias0 = *(const float4*)&bias[c0];
    float4 bias1 = *(const float4*)&bias[c0 + 4];

#pragma unroll
    for (int i2 = 0; i2 < 4; i2++) {
        float2 u[8];
#pragma unroll
        for (int j = 0; j < 8; j++) u[j] = unpack2(acc[i2][j]);
        int r0 = rowBase + ty * 8 + 2 * i2;
        if (r0 < NN) {
            float4 o0 = make_float4(u[0].x + bias0.x, u[1].x + bias0.y,
                                    u[2].x + bias0.z, u[3].x + bias0.w);
            float4 o1 = make_float4(u[4].x + bias1.x, u[5].x + bias1.y,
                                    u[6].x + bias1.z, u[7].x + bias1.w);
            *(float4*)&out[r0 * OUTD + c0] = o0;
            *(float4*)&out[r0 * OUTD + c0 + 4] = o1;
        }
        if (r0 + 1 < NN) {
            float4 o0 = make_float4(u[0].y + bias0.x, u[1].y + bias0.y,
                                    u[2].y + bias0.z, u[3].y + bias0.w);
            float4 o1 = make_float4(u[4].y + bias1.x, u[5].y + bias1.y,
                                    u[6].y + bias1.z, u[7].y + bias1.w);
            *(float4*)&out[(r0 + 1) * OUTD + c0] = o0;
            *(float4*)&out[(r0 + 1) * OUTD + c0 + 4] = o1;
        }
    }
}

// ---------------- kernel 2: node-level relation transforms ----------------
// Per (node, head): 32x32 matvecs, inner dot via f32x2 (16 fma2 instead of 32 FFMA).
__global__ void __launch_bounds__(288) transform_kernel(
    const float* __restrict__ msg, const float* __restrict__ msg_cau,
    const float* __restrict__ cau_filter, const float* __restrict__ time_emb,
    const int* __restrict__ cau_type)
{
    __shared__ float k_s[32][32];
    __shared__ float v_s[32][32];
    __shared__ float vt_s[32][32];
    __shared__ int ct_s[32];

    int h = blockIdx.y;
    int nodeBase = blockIdx.x * 32;
    int tid = threadIdx.x;

    for (int idx = tid; idx < 32 * 32; idx += 288) {
        int n = idx >> 5, dcol = idx & 31;
        int gn = nodeBase + n;
        float kv = 0.f, vv = 0.f;
        if (gn < NN) {
            kv = g_K[gn * OUTD + h * 32 + dcol];
            vv = g_V[gn * OUTD + h * 32 + dcol];
        }
        k_s[n][dcol] = kv;
        v_s[n][dcol] = vv;
        vt_s[n][dcol] = vv + time_emb[h * 32 + dcol];
    }
    for (int idx = tid; idx < 32; idx += 288) {
        int gn = nodeBase + idx;
        ct_s[idx] = (gn < NN) ? cau_type[gn] : -1;
    }
    __syncthreads();

    int wid = tid >> 5, lane = tid & 31;
    const float* mat;
    const float (*srcm)[32];
    float* outp;
    int myct = -1;
    if (wid < 3) {
        mat = cau_filter + (wid * NH + h) * 1024;
        srcm = k_s; outp = g_MK; myct = wid;
    } else if (wid < 6) {
        int e = wid - 3;
        mat = msg + (e * NH + h) * 1024;
        srcm = v_s; outp = g_VAL + e * NN * OUTD;
    } else {
        int e = wid - 6;
        mat = msg_cau + (e * NH + h) * 1024;
        srcm = vt_s; outp = g_CVAL + e * NN * OUTD;
    }

    ull m2[16];
#pragma unroll
    for (int i = 0; i < 16; i++)
        m2[i] = pack2(mat[(2 * i) * 32 + lane], mat[(2 * i + 1) * 32 + lane]);

    for (int n = 0; n < 32; n++) {
        int gn = nodeBase + n;
        if (gn >= NN) break;
        if (myct >= 0 && ct_s[n] != myct) continue;
        ull acc = 0ull;
        const ull* row = (const ull*)&srcm[n][0];
#pragma unroll
        for (int i = 0; i < 16; i++)
            fma2(acc, row[i], m2[i]);
        float2 f = unpack2(acc);
        outp[gn * OUTD + h * 32 + lane] = f.x + f.y;
    }
}

// ---------------- kernel 3: edge logits + softmax denominators ----------------
// One warp per edge; lane l handles dims [l*4, l*4+4) and [128+l*4, 128+l*4+4)
// -> all LDG.128 cover full cache lines (4 lines per instruction).
// No segment-max: logits are O(1), exp() safe, softmax shift-invariant.
__global__ void __launch_bounds__(256) logits_kernel(
    const int* __restrict__ src, const int* __restrict__ dst,
    const float* __restrict__ pri, const float* __restrict__ pri_cau)
{
    int e = blockIdx.y;
    int edge = blockIdx.x * 8 + (threadIdx.x >> 5);
    if (edge >= EE) return;
    int lane = threadIdx.x & 31;
    int s = src[e * EE + edge];
    int d = dst[e * EE + edge];
    int off = lane * 4;

    const float* qp = g_Q + d * OUTD;
    const float* kp = g_K + s * OUTD;
    const float* mp = g_MK + s * OUTD;
    float4 qa = *(const float4*)(qp + off);
    float4 qb = *(const float4*)(qp + 128 + off);
    float4 ka = *(const float4*)(kp + off);
    float4 kb = *(const float4*)(kp + 128 + off);
    float4 ma = *(const float4*)(mp + off);
    float4 mb = *(const float4*)(mp + 128 + off);

    // head of first half = lane>>3, second half = 4 + lane>>3
    float p0 = qa.x * ka.x + qa.y * ka.y + qa.z * ka.z + qa.w * ka.w;
    float p1 = qb.x * kb.x + qb.y * kb.y + qb.z * kb.z + qb.w * kb.w;
    float m0 = qa.x * ma.x + qa.y * ma.y + qa.z * ma.z + qa.w * ma.w;
    float m1 = qb.x * mb.x + qb.y * mb.y + qb.z * mb.z + qb.w * mb.w;

#pragma unroll
    for (int sh = 1; sh <= 4; sh <<= 1) {
        p0 += __shfl_xor_sync(0xffffffffu, p0, sh);
        p1 += __shfl_xor_sync(0xffffffffu, p1, sh);
        m0 += __shfl_xor_sync(0xffffffffu, m0, sh);
        m1 += __shfl_xor_sync(0xffffffffu, m1, sh);
    }
    // now every lane in group g=lane>>3 holds sums for heads g (p0/m0) and g+4 (p1/m1)
    int g = lane >> 3;
    const float isdk = 0.17677669529663687f;  // 1/sqrt(32)
    float ea0 = expf(p0 * pri[e * NH + g] * isdk);
    float ea1 = expf(p1 * pri[e * NH + g + 4] * isdk);
    float ec0 = expf(m0 * pri_cau[e * NH + g] * isdk);
    float ec1 = expf(m1 * pri_cau[e * NH + g + 4] * isdk);

    // redistribute so lane h (0..7) holds head h, then one coalesced 64B row
    int srcl = (lane & 3) * 8;
    float va0 = __shfl_sync(0xffffffffu, ea0, srcl);
    float va1 = __shfl_sync(0xffffffffu, ea1, srcl);
    float vc0 = __shfl_sync(0xffffffffu, ec0, srcl);
    float vc1 = __shfl_sync(0xffffffffu, ec1, srcl);

    if (lane < NH) {
        float ea = (lane < 4) ? va0 : va1;
        float ec = (lane < 4) ? vc0 : vc1;
        int eidx = e * EE + edge;
        g_E[eidx * NH + lane] = make_float2(ea, ec);
        red_add_v2(&g_S[(e * NN + d) * NH + lane], ea, ec);
    }
}

// ---------------- kernel 4: weighted aggregation ----------------
// One warp per edge, contiguous lane layout, full-line red.v4 into d_out.
__global__ void __launch_bounds__(256) aggregate_kernel(
    const int* __restrict__ src, const int* __restrict__ dst,
    const float* __restrict__ comb_pri, float* __restrict__ out)
{
    int e = blockIdx.y;
    int edge = blockIdx.x * 8 + (threadIdx.x >> 5);
    if (edge >= EE) return;
    int lane = threadIdx.x & 31;
    int s = src[e * EE + edge];
    int d = dst[e * EE + edge];
    int h0 = lane >> 3;
    int h1 = h0 + 4;
    int eidx = e * EE + edge;

    float2 eh0 = g_E[eidx * NH + h0];
    float2 eh1 = g_E[eidx * NH + h1];
    float2 s0 = g_S[(e * NN + d) * NH + h0];
    float2 s1 = g_S[(e * NN + d) * NH + h1];
    float wa0 = __fdividef(eh0.x, s0.x);
    float wc0 = __fdividef(eh0.y, s0.y);
    float wa1 = __fdividef(eh1.x, s1.x);
    float wc1 = __fdividef(eh1.y, s1.y);

    int off = lane * 4;
    const float* vp = g_VAL  + e * NN * OUTD + s * OUTD;
    const float* cp = g_CVAL + e * NN * OUTD + s * OUTD;
    float4 v0 = *(const float4*)(vp + off);
    float4 v1 = *(const float4*)(vp + 128 + off);
    float4 c0 = *(const float4*)(cp + off);
    float4 c1 = *(const float4*)(cp + 128 + off);
    float4 b0 = *(const float4*)&comb_pri[e * OUTD + off];
    float4 b1 = *(const float4*)&comb_pri[e * OUTD + 128 + off];

    float r0 = wa0 * v0.x + wc0 * b0.x * c0.x;
    float r1 = wa0 * v0.y + wc0 * b0.y * c0.y;
    float r2 = wa0 * v0.z + wc0 * b0.z * c0.z;
    float r3 = wa0 * v0.w + wc0 * b0.w * c0.w;
    float r4 = wa1 * v1.x + wc1 * b1.x * c1.x;
    float r5 = wa1 * v1.y + wc1 * b1.y * c1.y;
    float r6 = wa1 * v1.z + wc1 * b1.z * c1.z;
    float r7 = wa1 * v1.w + wc1 * b1.w * c1.w;

    float* op = out + d * OUTD;
    red_add_v4(op + off, r0, r1, r2, r3);
    red_add_v4(op + 128 + off, r4, r5, r6, r7);
}

// ---------------- kernel 5: finalize (mean over 3 etypes + relu) ----------------
__global__ void finalize_kernel(float* __restrict__ out) {
    int i = blockIdx.x * blockDim.x + threadIdx.x;
    if (i < NN * OUTD) {
        float v = out[i] * (1.0f / 3.0f);
        out[i] = v > 0.0f ? v : 0.0f;
    }
}

// ---------------- launch ----------------
extern "C" void kernel_launch(void* const* d_in, const int* in_sizes, int n_in,
                              void* d_out, int out_size) {
    const float* x          = (const float*)d_in[0];
    const float* Wk         = (const float*)d_in[1];
    const float* bk         = (const float*)d_in[2];
    const float* Wq         = (const float*)d_in[3];
    const float* bq         = (const float*)d_in[4];
    const float* Wv         = (const float*)d_in[5];
    const float* bv         = (const float*)d_in[6];
    const float* pri        = (const float*)d_in[7];
    const float* msg        = (const float*)d_in[8];
    const float* pri_cau    = (const float*)d_in[9];
    const float* msg_cau    = (const float*)d_in[10];
    const float* comb_pri   = (const float*)d_in[11];
    const float* cau_filter = (const float*)d_in[12];
    const float* time_emb   = (const float*)d_in[13];
    const int*   cau_type   = (const int*)d_in[14];
    const int*   src        = (const int*)d_in[15];
    const int*   dst        = (const int*)d_in[16];
    float* out = (float*)d_out;

    zero_kernel<<<2048, 256>>>(out);

    dim3 ggrid(768 / BN, (NN + BM - 1) / BM);
    gemm_qkv<<<ggrid, 256>>>(x, Wk, bk, Wq, bq, Wv, bv);

    dim3 tgrid((NN + 31) / 32, NH);
    transform_kernel<<<tgrid, 288>>>(msg, msg_cau, cau_filter, time_emb, cau_type);

    dim3 egrid((EE + 7) / 8, 3);
    logits_kernel<<<egrid, 256>>>(src, dst, pri, pri_cau);
    aggregate_kernel<<<egrid, 256>>>(src, dst, comb_pri, out);

    finalize_kernel<<<(NN * OUTD + 255) / 256, 256>>>(out);
}